// round 2
// baseline (speedup 1.0000x reference)
#include <cuda_runtime.h>
#include <cuda_pipeline.h>

#define BB 16
#define LL 512
#define NK 48
#define EE 128
#define DD 384
#define HH 128

// Per-token dG * mask, reduced deterministically by the finalize kernel.
__device__ float g_dG[BB * LL];

// ---------------- packed f32x2 helpers ----------------
__device__ __forceinline__ unsigned long long ffma2(unsigned long long a,
                                                    unsigned long long b,
                                                    unsigned long long c) {
    unsigned long long d;
    asm("fma.rn.f32x2 %0, %1, %2, %3;" : "=l"(d) : "l"(a), "l"(b), "l"(c));
    return d;
}
__device__ __forceinline__ unsigned long long pack2(float lo, float hi) {
    unsigned long long d;
    asm("mov.b64 %0, {%1, %2};" : "=l"(d) : "f"(lo), "f"(hi));
    return d;
}
__device__ __forceinline__ unsigned long long pack2dup(float v) {
    unsigned long long d;
    asm("mov.b64 %0, {%1, %1};" : "=l"(d) : "f"(v));
    return d;
}
__device__ __forceinline__ float2 unpack2(unsigned long long v) {
    float lo, hi;
    asm("mov.b64 {%0, %1}, %2;" : "=f"(lo), "=f"(hi) : "l"(v));
    return make_float2(lo, hi);
}

__device__ __forceinline__ float gelu_erf(float x) {
    return 0.5f * x * (1.0f + erff(x * 0.70710678118654752440f));
}

// ---------------- fused GEMM block ----------------
// C[48][384] (+bias, preloaded into acc) += A[48][KTOT] @ W[KTOT][384]
// A in SMEM (row stride ASTRIDE), W streamed from global in 16x384 k-slabs,
// double-buffered via cp.async. Thread (ty,tx) owns rows ty*3..+2 and cols
// {g*64 + tx*4 + j : g<6, j<4}, packed as f32x2 pairs: acc[i][2g+h].
template <int KTOT, int ASTRIDE>
__device__ __forceinline__ void gemm_block(const float* __restrict__ gW,
                                           const float* __restrict__ aSrc,
                                           float* sWbuf,  // 2 * 6144 floats
                                           unsigned long long acc[3][12],
                                           int tx, int ty, int tid) {
    constexpr int NC = KTOT / 16;
    // prefetch slab 0
    {
        const float* src = gW;
        float* dst = sWbuf;
#pragma unroll
        for (int p = 0; p < 6; ++p)
            __pipeline_memcpy_async(&dst[tid * 4 + p * 1024],
                                    &src[tid * 4 + p * 1024], 16);
        __pipeline_commit();
    }
#pragma unroll 1
    for (int c = 0; c < NC; ++c) {
        if (c + 1 < NC) {
            const float* src = gW + (size_t)(c + 1) * 16 * DD;
            float* dst = sWbuf + ((c + 1) & 1) * 6144;
#pragma unroll
            for (int p = 0; p < 6; ++p)
                __pipeline_memcpy_async(&dst[tid * 4 + p * 1024],
                                        &src[tid * 4 + p * 1024], 16);
            __pipeline_commit();
            __pipeline_wait_prior(1);
        } else {
            __pipeline_wait_prior(0);
        }
        __syncthreads();
        const float* wbuf = sWbuf + (c & 1) * 6144;
        const float* a0p = aSrc + (ty * 3 + 0) * ASTRIDE + c * 16;
        const float* a1p = aSrc + (ty * 3 + 1) * ASTRIDE + c * 16;
        const float* a2p = aSrc + (ty * 3 + 2) * ASTRIDE + c * 16;
#pragma unroll 4
        for (int k = 0; k < 16; ++k) {
            unsigned long long a0 = pack2dup(a0p[k]);
            unsigned long long a1 = pack2dup(a1p[k]);
            unsigned long long a2 = pack2dup(a2p[k]);
#pragma unroll
            for (int g = 0; g < 6; ++g) {
                ulonglong2 w =
                    *(const ulonglong2*)&wbuf[k * DD + g * 64 + tx * 4];
                acc[0][2 * g]     = ffma2(a0, w.x, acc[0][2 * g]);
                acc[0][2 * g + 1] = ffma2(a0, w.y, acc[0][2 * g + 1]);
                acc[1][2 * g]     = ffma2(a1, w.x, acc[1][2 * g]);
                acc[1][2 * g + 1] = ffma2(a1, w.y, acc[1][2 * g + 1]);
                acc[2][2 * g]     = ffma2(a2, w.x, acc[2][2 * g]);
                acc[2][2 * g + 1] = ffma2(a2, w.y, acc[2][2 * g + 1]);
            }
        }
        __syncthreads();
    }
}

// SMEM layout (floats):
// sA   [48*128]  = 6144     : h_E tile
// sW   [2*6144]  = 12288    : weight slab double buffer / later red[16][384]
// sT   [48*384]  = 18432    : gelu(GEMM1) intermediate
// sH   [384], sH1[128], sH2[64], sIdx[48]
#define SMEM_FLOATS (6144 + 12288 + 18432 + 384 + 128 + 64 + 48)

__global__ void __launch_bounds__(256, 1)
schnet_main(const float* __restrict__ h_V, const float* __restrict__ h_E,
            const float* __restrict__ mask, const float* __restrict__ fw1,
            const float* __restrict__ fb1, const float* __restrict__ fw2,
            const float* __restrict__ fb2, const float* __restrict__ hw1,
            const float* __restrict__ hb1, const float* __restrict__ hw2,
            const float* __restrict__ hb2, const float* __restrict__ hw3,
            const float* __restrict__ hb3, const int* __restrict__ E_idx) {
    extern __shared__ float smem[];
    float* sA = smem;               // 6144
    float* sW = sA + 6144;          // 12288 (2 slabs)
    float* sT = sW + 12288;         // 18432
    float* sH = sT + 18432;         // 384
    float* sH1 = sH + 384;          // 128
    float* sH2 = sH1 + 128;         // 64
    int* sIdx = (int*)(sH2 + 64);   // 48

    const int l = blockIdx.x;
    const int b = blockIdx.y;
    const int tid = threadIdx.x;
    const int tx = tid & 15;
    const int ty = tid >> 4;
    const size_t tok = (size_t)b * LL + l;

    // stage h_E tile [48][128] (row-major, contiguous)
    {
        const float4* src = (const float4*)(h_E + tok * (NK * EE));
        float4* dst = (float4*)sA;
#pragma unroll
        for (int p = 0; p < 6; ++p) dst[tid + p * 256] = src[tid + p * 256];
    }
    if (tid < NK) sIdx[tid] = E_idx[tok * NK + tid];

    // ---------------- GEMM1: t1 = gelu(h_E @ fw1 + fb1) ----------------
    unsigned long long acc[3][12];
#pragma unroll
    for (int g = 0; g < 6; ++g) {
        float4 bv = *(const float4*)&fb1[g * 64 + tx * 4];
        unsigned long long p0 = pack2(bv.x, bv.y), p1 = pack2(bv.z, bv.w);
#pragma unroll
        for (int i = 0; i < 3; ++i) {
            acc[i][2 * g] = p0;
            acc[i][2 * g + 1] = p1;
        }
    }
    gemm_block<EE, EE>(fw1, sA, sW, acc, tx, ty, tid);

    // gelu + store t1 to SMEM
#pragma unroll
    for (int i = 0; i < 3; ++i) {
        int row = ty * 3 + i;
#pragma unroll
        for (int g = 0; g < 6; ++g) {
            float2 v0 = unpack2(acc[i][2 * g]);
            float2 v1 = unpack2(acc[i][2 * g + 1]);
            float4 o;
            o.x = gelu_erf(v0.x);
            o.y = gelu_erf(v0.y);
            o.z = gelu_erf(v1.x);
            o.w = gelu_erf(v1.y);
            *(float4*)&sT[row * DD + g * 64 + tx * 4] = o;
        }
    }
    __syncthreads();

    // ---------------- GEMM2: W = gelu(t1 @ fw2 + fb2) ----------------
#pragma unroll
    for (int g = 0; g < 6; ++g) {
        float4 bv = *(const float4*)&fb2[g * 64 + tx * 4];
        unsigned long long p0 = pack2(bv.x, bv.y), p1 = pack2(bv.z, bv.w);
#pragma unroll
        for (int i = 0; i < 3; ++i) {
            acc[i][2 * g] = p0;
            acc[i][2 * g + 1] = p1;
        }
    }
    gemm_block<DD, DD>(fw2, sT, sW, acc, tx, ty, tid);

    // ---------------- gather x_j and weighted neighbor sum ----------------
    float part[6][4];
#pragma unroll
    for (int g = 0; g < 6; ++g)
#pragma unroll
        for (int j = 0; j < 4; ++j) part[g][j] = 0.0f;

#pragma unroll
    for (int i = 0; i < 3; ++i) {
        int row = ty * 3 + i;
        const float* xv = h_V + ((size_t)b * LL + sIdx[row]) * DD;
#pragma unroll
        for (int g = 0; g < 6; ++g) {
            float2 v0 = unpack2(acc[i][2 * g]);
            float2 v1 = unpack2(acc[i][2 * g + 1]);
            float w0 = gelu_erf(v0.x);
            float w1 = gelu_erf(v0.y);
            float w2 = gelu_erf(v1.x);
            float w3 = gelu_erf(v1.y);
            float4 x = *(const float4*)&xv[g * 64 + tx * 4];
            part[g][0] += w0 * x.x;
            part[g][1] += w1 * x.y;
            part[g][2] += w2 * x.z;
            part[g][3] += w3 * x.w;
        }
    }

    // reduce the 16 ty-partials per column through SMEM (reuse sW as red[16][384])
    float* red = sW;
#pragma unroll
    for (int g = 0; g < 6; ++g)
        *(float4*)&red[ty * DD + g * 64 + tx * 4] =
            make_float4(part[g][0], part[g][1], part[g][2], part[g][3]);
    __syncthreads();
    for (int c = tid; c < DD; c += 256) {
        float s = 0.0f;
#pragma unroll
        for (int r = 0; r < 16; ++r) s += red[r * DD + c];
        sH[c] = s;
    }
    __syncthreads();

    // ---------------- MLP head ----------------
    if (tid < HH) {
        float a = hb1[tid];
#pragma unroll 8
        for (int d = 0; d < DD; ++d) a += sH[d] * hw1[d * HH + tid];
        sH1[tid] = gelu_erf(a);
    }
    __syncthreads();
    if (tid < HH / 2) {
        float a = hb2[tid];
#pragma unroll 8
        for (int d = 0; d < HH; ++d) a += sH1[d] * hw2[d * (HH / 2) + tid];
        sH2[tid] = gelu_erf(a);
    }
    __syncthreads();
    if (tid < 32) {
        float a = sH2[tid] * hw3[tid] + sH2[tid + 32] * hw3[tid + 32];
#pragma unroll
        for (int o = 16; o > 0; o >>= 1) a += __shfl_down_sync(0xffffffffu, a, o);
        if (tid == 0) {
            float dG = a + hb3[0];
            g_dG[tok] = dG * mask[tok];
        }
    }
}

__global__ void schnet_finalize(const float* __restrict__ mask,
                                float* __restrict__ out) {
    __shared__ float sm[512];
    __shared__ float sd[512];
    const int b = blockIdx.x;
    const int t = threadIdx.x;
    sm[t] = mask[b * LL + t];
    sd[t] = g_dG[b * LL + t];
    __syncthreads();
    for (int s = 256; s > 0; s >>= 1) {
        if (t < s) {
            sm[t] += sm[t + s];
            sd[t] += sd[t + s];
        }
        __syncthreads();
    }
    if (t == 0) {
        float vl = fmaxf(sm[0], 1.0f);
        out[b] = sd[0] / sqrtf(vl);
    }
}

extern "C" void kernel_launch(void* const* d_in, const int* in_sizes, int n_in,
                              void* d_out, int out_size) {
    const float* h_V  = (const float*)d_in[0];
    const float* h_E  = (const float*)d_in[1];
    const float* mask = (const float*)d_in[2];
    const float* fw1  = (const float*)d_in[3];
    const float* fb1  = (const float*)d_in[4];
    const float* fw2  = (const float*)d_in[5];
    const float* fb2  = (const float*)d_in[6];
    const float* hw1  = (const float*)d_in[7];
    const float* hb1  = (const float*)d_in[8];
    const float* hw2  = (const float*)d_in[9];
    const float* hb2  = (const float*)d_in[10];
    const float* hw3  = (const float*)d_in[11];
    const float* hb3  = (const float*)d_in[12];
    const int*   E_idx = (const int*)d_in[13];

    const int smem_bytes = SMEM_FLOATS * (int)sizeof(float);
    cudaFuncSetAttribute(schnet_main, cudaFuncAttributeMaxDynamicSharedMemorySize,
                         smem_bytes);

    dim3 grid(LL, BB);
    schnet_main<<<grid, 256, smem_bytes>>>(h_V, h_E, mask, fw1, fb1, fw2, fb2,
                                           hw1, hb1, hw2, hb2, hw3, hb3, E_idx);
    schnet_finalize<<<BB, 512>>>(mask, (float*)d_out);
}

// round 5
// speedup vs baseline: 2.1404x; 2.1404x over previous
#include <cuda_runtime.h>
#include <cuda_pipeline.h>

#define BB 16
#define LL 512
#define NK 48
#define EE 128
#define DD 384
#define HH 128

// Per-token dG * mask, reduced deterministically by the finalize kernel.
__device__ float g_dG[BB * LL];

// ---------------- packed f32x2 helpers ----------------
__device__ __forceinline__ unsigned long long ffma2(unsigned long long a,
                                                    unsigned long long b,
                                                    unsigned long long c) {
    unsigned long long d;
    asm("fma.rn.f32x2 %0, %1, %2, %3;" : "=l"(d) : "l"(a), "l"(b), "l"(c));
    return d;
}
__device__ __forceinline__ unsigned long long pack2(float lo, float hi) {
    unsigned long long d;
    asm("mov.b64 %0, {%1, %2};" : "=l"(d) : "f"(lo), "f"(hi));
    return d;
}
__device__ __forceinline__ unsigned long long pack2dup(float v) {
    unsigned long long d;
    asm("mov.b64 %0, {%1, %1};" : "=l"(d) : "f"(v));
    return d;
}
__device__ __forceinline__ float2 unpack2(unsigned long long v) {
    float lo, hi;
    asm("mov.b64 {%0, %1}, %2;" : "=f"(lo), "=f"(hi) : "l"(v));
    return make_float2(lo, hi);
}

__device__ __forceinline__ float gelu_erf(float x) {
    return 0.5f * x * (1.0f + erff(x * 0.70710678118654752440f));
}

// ---------------- fused GEMM block (6 rows x 12 cols per thread) ----------------
// C[48][384] (+bias preloaded in acc) += A[48][KTOT] @ W[KTOT][384]
// tx = tid&31 (0..31): cols {tx*4 + 128*j + e : j<3, e<4}
// ty = tid>>5 (0..7): rows ty*6 .. ty*6+5  (warp == one ty -> A loads broadcast)
// acc[i][m]: i=row, m = 2*j + h  (h selects low/high f32x2 pair of the float4)
// W streamed from global in 16x384 k-slabs, double-buffered via cp.async.
template <int KTOT, int ASTRIDE>
__device__ __forceinline__ void gemm_block(const float* __restrict__ gW,
                                           const float* __restrict__ aSrc,
                                           float* sWbuf,  // 2 * 6144 floats
                                           unsigned long long acc[6][6],
                                           int tx, int ty, int tid) {
    constexpr int NC = KTOT / 16;
    // prefetch slab 0
    {
        const float* src = gW;
        float* dst = sWbuf;
#pragma unroll
        for (int p = 0; p < 6; ++p)
            __pipeline_memcpy_async(&dst[tid * 4 + p * 1024],
                                    &src[tid * 4 + p * 1024], 16);
        __pipeline_commit();
    }
#pragma unroll 1
    for (int c = 0; c < NC; ++c) {
        if (c + 1 < NC) {
            const float* src = gW + (size_t)(c + 1) * 16 * DD;
            float* dst = sWbuf + ((c + 1) & 1) * 6144;
#pragma unroll
            for (int p = 0; p < 6; ++p)
                __pipeline_memcpy_async(&dst[tid * 4 + p * 1024],
                                        &src[tid * 4 + p * 1024], 16);
            __pipeline_commit();
            __pipeline_wait_prior(1);
        } else {
            __pipeline_wait_prior(0);
        }
        __syncthreads();
        const float* wbuf = sWbuf + (c & 1) * 6144;
        const float* abase = aSrc + (ty * 6) * ASTRIDE + c * 16;
#pragma unroll
        for (int kq = 0; kq < 4; ++kq) {
            float av[6][4];
#pragma unroll
            for (int i = 0; i < 6; ++i)
                *(float4*)&av[i][0] =
                    *(const float4*)&abase[i * ASTRIDE + kq * 4];
#pragma unroll
            for (int kk = 0; kk < 4; ++kk) {
                const int k = kq * 4 + kk;
                ulonglong2 W0 = *(const ulonglong2*)&wbuf[k * DD + tx * 4];
                ulonglong2 W1 =
                    *(const ulonglong2*)&wbuf[k * DD + 128 + tx * 4];
                ulonglong2 W2 =
                    *(const ulonglong2*)&wbuf[k * DD + 256 + tx * 4];
#pragma unroll
                for (int i = 0; i < 6; ++i) {
                    unsigned long long a = pack2dup(av[i][kk]);
                    acc[i][0] = ffma2(a, W0.x, acc[i][0]);
                    acc[i][1] = ffma2(a, W0.y, acc[i][1]);
                    acc[i][2] = ffma2(a, W1.x, acc[i][2]);
                    acc[i][3] = ffma2(a, W1.y, acc[i][3]);
                    acc[i][4] = ffma2(a, W2.x, acc[i][4]);
                    acc[i][5] = ffma2(a, W2.y, acc[i][5]);
                }
            }
        }
        __syncthreads();
    }
}

// SMEM layout (floats):
// sA   6144 : h_E tile [48][128]
// sW   12288: weight slab double buffer / later red[8][384] (uses first 3072)
// sT   18432: gelu(GEMM1) intermediate [48][384]
// sH 384, sH1 128, sH2 64, sP 256, sP2 256, sIdx 48
#define SMEM_FLOATS (6144 + 12288 + 18432 + 384 + 128 + 64 + 256 + 256 + 48)

__global__ void __launch_bounds__(256, 1)
schnet_main(const float* __restrict__ h_V, const float* __restrict__ h_E,
            const float* __restrict__ mask, const float* __restrict__ fw1,
            const float* __restrict__ fb1, const float* __restrict__ fw2,
            const float* __restrict__ fb2, const float* __restrict__ hw1,
            const float* __restrict__ hb1, const float* __restrict__ hw2,
            const float* __restrict__ hb2, const float* __restrict__ hw3,
            const float* __restrict__ hb3, const int* __restrict__ E_idx) {
    extern __shared__ float smem[];
    float* sA = smem;                // 6144
    float* sW = sA + 6144;           // 12288 (2 slabs)
    float* sT = sW + 12288;          // 18432
    float* sH = sT + 18432;          // 384
    float* sH1 = sH + 384;           // 128
    float* sH2 = sH1 + 128;          // 64
    float* sP = sH2 + 64;            // 256
    float* sP2 = sP + 256;           // 256
    int* sIdx = (int*)(sP2 + 256);   // 48

    const int l = blockIdx.x;
    const int b = blockIdx.y;
    const int tid = threadIdx.x;
    const int tx = tid & 31;
    const int ty = tid >> 5;
    const size_t tok = (size_t)b * LL + l;

    // stage h_E tile [48][128] (row-major, contiguous)
    {
        const float4* src = (const float4*)(h_E + tok * (NK * EE));
        float4* dst = (float4*)sA;
#pragma unroll
        for (int p = 0; p < 6; ++p) dst[tid + p * 256] = src[tid + p * 256];
    }
    if (tid < NK) sIdx[tid] = E_idx[tok * NK + tid];

    // ---------------- GEMM1: t1 = gelu(h_E @ fw1 + fb1) ----------------
    unsigned long long acc[6][6];
#pragma unroll
    for (int j = 0; j < 3; ++j) {
        float4 bv = *(const float4*)&fb1[j * 128 + tx * 4];
        unsigned long long p0 = pack2(bv.x, bv.y), p1 = pack2(bv.z, bv.w);
#pragma unroll
        for (int i = 0; i < 6; ++i) {
            acc[i][2 * j] = p0;
            acc[i][2 * j + 1] = p1;
        }
    }
    gemm_block<EE, EE>(fw1, sA, sW, acc, tx, ty, tid);

    // gelu + store t1 to SMEM
#pragma unroll
    for (int i = 0; i < 6; ++i) {
        int row = ty * 6 + i;
#pragma unroll
        for (int j = 0; j < 3; ++j) {
            float2 v0 = unpack2(acc[i][2 * j]);
            float2 v1 = unpack2(acc[i][2 * j + 1]);
            float4 o;
            o.x = gelu_erf(v0.x);
            o.y = gelu_erf(v0.y);
            o.z = gelu_erf(v1.x);
            o.w = gelu_erf(v1.y);
            *(float4*)&sT[row * DD + j * 128 + tx * 4] = o;
        }
    }
    __syncthreads();

    // ---------------- GEMM2: W = gelu(t1 @ fw2 + fb2) ----------------
#pragma unroll
    for (int j = 0; j < 3; ++j) {
        float4 bv = *(const float4*)&fb2[j * 128 + tx * 4];
        unsigned long long p0 = pack2(bv.x, bv.y), p1 = pack2(bv.z, bv.w);
#pragma unroll
        for (int i = 0; i < 6; ++i) {
            acc[i][2 * j] = p0;
            acc[i][2 * j + 1] = p1;
        }
    }
    gemm_block<DD, DD>(fw2, sT, sW, acc, tx, ty, tid);

    // ---------------- gather x_j and weighted neighbor sum ----------------
    float4 part[3];
#pragma unroll
    for (int j = 0; j < 3; ++j) part[j] = make_float4(0.f, 0.f, 0.f, 0.f);

#pragma unroll
    for (int i = 0; i < 6; ++i) {
        int row = ty * 6 + i;
        const float* xv = h_V + ((size_t)b * LL + sIdx[row]) * DD;
#pragma unroll
        for (int j = 0; j < 3; ++j) {
            float2 v0 = unpack2(acc[i][2 * j]);
            float2 v1 = unpack2(acc[i][2 * j + 1]);
            float w0 = gelu_erf(v0.x);
            float w1 = gelu_erf(v0.y);
            float w2 = gelu_erf(v1.x);
            float w3 = gelu_erf(v1.y);
            float4 x = *(const float4*)&xv[j * 128 + tx * 4];
            part[j].x += w0 * x.x;
            part[j].y += w1 * x.y;
            part[j].z += w2 * x.z;
            part[j].w += w3 * x.w;
        }
    }

    // reduce the 8 ty-partials per column through SMEM (reuse sW as red[8][384])
    float* red = sW;
#pragma unroll
    for (int j = 0; j < 3; ++j)
        *(float4*)&red[ty * DD + j * 128 + tx * 4] = part[j];
    __syncthreads();
    for (int c = tid; c < DD; c += 256) {
        float s = 0.0f;
#pragma unroll
        for (int r = 0; r < 8; ++r) s += red[r * DD + c];
        sH[c] = s;
    }
    __syncthreads();

    // ---------------- MLP head (split-K across all 256 threads) ----------
    // layer 1: 128 outputs, K=384 -> 2 partials of 192
    {
        int o = tid & 127, h = tid >> 7;
        float a = 0.0f;
        const int d0 = h * 192;
#pragma unroll 8
        for (int d = 0; d < 192; ++d) a += sH[d0 + d] * hw1[(d0 + d) * HH + o];
        sP[h * 128 + o] = a;
    }
    __syncthreads();
    if (tid < HH) sH1[tid] = gelu_erf(hb1[tid] + sP[tid] + sP[128 + tid]);
    __syncthreads();
    // layer 2: 64 outputs, K=128 -> 4 partials of 32
    {
        int o = tid & 63, q = tid >> 6;
        float a = 0.0f;
        const int d0 = q * 32;
#pragma unroll 8
        for (int d = 0; d < 32; ++d)
            a += sH1[d0 + d] * hw2[(d0 + d) * (HH / 2) + o];
        sP2[q * 64 + o] = a;
    }
    __syncthreads();
    if (tid < HH / 2)
        sH2[tid] = gelu_erf(hb2[tid] + sP2[tid] + sP2[64 + tid] +
                            sP2[128 + tid] + sP2[192 + tid]);
    __syncthreads();
    if (tid < 32) {
        float a = sH2[tid] * hw3[tid] + sH2[tid + 32] * hw3[tid + 32];
#pragma unroll
        for (int o = 16; o > 0; o >>= 1) a += __shfl_down_sync(0xffffffffu, a, o);
        if (tid == 0) {
            float dG = a + hb3[0];
            g_dG[tok] = dG * mask[tok];
        }
    }
}

__global__ void schnet_finalize(const float* __restrict__ mask,
                                float* __restrict__ out) {
    __shared__ float sm[512];
    __shared__ float sd[512];
    const int b = blockIdx.x;
    const int t = threadIdx.x;
    sm[t] = mask[b * LL + t];
    sd[t] = g_dG[b * LL + t];
    __syncthreads();
    for (int s = 256; s > 0; s >>= 1) {
        if (t < s) {
            sm[t] += sm[t + s];
            sd[t] += sd[t + s];
        }
        __syncthreads();
    }
    if (t == 0) {
        float vl = fmaxf(sm[0], 1.0f);
        out[b] = sd[0] / sqrtf(vl);
    }
}

extern "C" void kernel_launch(void* const* d_in, const int* in_sizes, int n_in,
                              void* d_out, int out_size) {
    const float* h_V  = (const float*)d_in[0];
    const float* h_E  = (const float*)d_in[1];
    const float* mask = (const float*)d_in[2];
    const float* fw1  = (const float*)d_in[3];
    const float* fb1  = (const float*)d_in[4];
    const float* fw2  = (const float*)d_in[5];
    const float* fb2  = (const float*)d_in[6];
    const float* hw1  = (const float*)d_in[7];
    const float* hb1  = (const float*)d_in[8];
    const float* hw2  = (const float*)d_in[9];
    const float* hb2  = (const float*)d_in[10];
    const float* hw3  = (const float*)d_in[11];
    const float* hb3  = (const float*)d_in[12];
    const int*   E_idx = (const int*)d_in[13];

    const int smem_bytes = SMEM_FLOATS * (int)sizeof(float);
    cudaFuncSetAttribute(schnet_main, cudaFuncAttributeMaxDynamicSharedMemorySize,
                         smem_bytes);

    dim3 grid(LL, BB);
    schnet_main<<<grid, 256, smem_bytes>>>(h_V, h_E, mask, fw1, fb1, fw2, fb2,
                                           hw1, hb1, hw2, hb2, hw3, hb3, E_idx);
    schnet_finalize<<<BB, 512>>>(mask, (float*)d_out);
}